// round 2
// baseline (speedup 1.0000x reference)
#include <cuda_runtime.h>
#include <cuda_fp16.h>
#include <cstdint>

// ============================================================================
// out[8192,4096] = fwht(x) @ W^T + b  ==  x @ fwht(W)^T + b   (H symmetric)
//  K1: Wh = fp16(fwht(W rows) / 64)
//  K2: Xh = fp16(x)
//  K3: fp16 HMMA GEMM (mma.sync m16n8k16, fp32 accum), 256x128 tile,
//      4-stage cp.async pipeline, SW128 smem swizzle, fused bias.
// (tcgen05 is unavailable: harness compiles for plain sm_103, not sm_103a.)
// ============================================================================

#define M_TOTAL 8192
#define N_TOTAL 4096
#define K_TOTAL 4096

#define TILE_M 256
#define TILE_N 128
#define KS 64                       // halfs of K per stage (128B row)
#define STAGES 4
#define K_ITERS (K_TOTAL / KS)      // 64

#define A_STAGE_BYTES (TILE_M * 128)          // 32768
#define B_STAGE_BYTES (TILE_N * 128)          // 16384
#define STAGE_BYTES   (A_STAGE_BYTES + B_STAGE_BYTES)
#define SMEM_TOTAL    (STAGES * STAGE_BYTES)  // 196608

// scratch (device globals: allocation-free)
__device__ __align__(1024) __half g_Wh[(size_t)N_TOTAL * K_TOTAL];
__device__ __align__(1024) __half g_Xh[(size_t)M_TOTAL * K_TOTAL];

// ---------------------------------------------------------------------------
__device__ __forceinline__ uint32_t smem_u32(const void* p) {
    uint32_t a;
    asm("{ .reg .u64 t; cvta.to.shared.u64 t, %1; cvt.u32.u64 %0, t; }"
        : "=r"(a) : "l"(p));
    return a;
}
__device__ __forceinline__ void cp_async16(uint32_t dst, const void* src) {
    asm volatile("cp.async.cg.shared.global [%0], [%1], 16;"
                 :: "r"(dst), "l"(src));
}
__device__ __forceinline__ void cp_commit() {
    asm volatile("cp.async.commit_group;" ::: "memory");
}
__device__ __forceinline__ void cp_wait2() {
    asm volatile("cp.async.wait_group 2;" ::: "memory");
}
__device__ __forceinline__ void ldsm_x4(uint32_t& r0, uint32_t& r1,
                                        uint32_t& r2, uint32_t& r3, uint32_t a) {
    asm volatile("ldmatrix.sync.aligned.m8n8.x4.shared.b16 {%0,%1,%2,%3}, [%4];"
                 : "=r"(r0), "=r"(r1), "=r"(r2), "=r"(r3) : "r"(a));
}
__device__ __forceinline__ void mma16816(float* c, const uint32_t* a,
                                         uint32_t b0, uint32_t b1) {
    asm volatile(
        "mma.sync.aligned.m16n8k16.row.col.f32.f16.f16.f32 "
        "{%0,%1,%2,%3}, {%4,%5,%6,%7}, {%8,%9}, {%0,%1,%2,%3};"
        : "+f"(c[0]), "+f"(c[1]), "+f"(c[2]), "+f"(c[3])
        : "r"(a[0]), "r"(a[1]), "r"(a[2]), "r"(a[3]), "r"(b0), "r"(b1));
}
// SW128 swizzle: tile rows are 128B; byte offset within tile
__device__ __forceinline__ uint32_t swz(int row, int cb) {
    return (uint32_t)(row * 128 + (cb ^ ((row & 7) << 4)));
}

// ---------------------------------------------------------------------------
// K1: per-row FWHT of W, scale 1/sqrt(4096), -> fp16
// ---------------------------------------------------------------------------
__global__ void __launch_bounds__(256) fwht_w_kernel(const float* __restrict__ W,
                                                     __half* __restrict__ Wh) {
    __shared__ float s[4096];
    const int tid = threadIdx.x;
    const float* src = W + (size_t)blockIdx.x * 4096;
    #pragma unroll
    for (int i = tid; i < 4096; i += 256) s[i] = src[i];
    __syncthreads();
    for (int h = 1; h < 4096; h <<= 1) {
        #pragma unroll 4
        for (int p = tid; p < 2048; p += 256) {
            int i = ((p & ~(h - 1)) << 1) | (p & (h - 1));
            float a = s[i], b = s[i + h];
            s[i] = a + b;
            s[i + h] = a - b;
        }
        __syncthreads();
    }
    __half* dst = Wh + (size_t)blockIdx.x * 4096;
    #pragma unroll
    for (int i = tid; i < 4096; i += 256)
        dst[i] = __float2half(s[i] * 0.015625f);
}

// ---------------------------------------------------------------------------
// K2: x fp32 -> fp16
// ---------------------------------------------------------------------------
__global__ void __launch_bounds__(256) convert_x_kernel(const float4* __restrict__ x,
                                                        __half2* __restrict__ xh,
                                                        int n4) {
    int i = blockIdx.x * blockDim.x + threadIdx.x;
    int stride = gridDim.x * blockDim.x;
    for (; i < n4; i += stride) {
        float4 v = x[i];
        xh[2 * i]     = __floats2half2_rn(v.x, v.y);
        xh[2 * i + 1] = __floats2half2_rn(v.z, v.w);
    }
}

// ---------------------------------------------------------------------------
// K3: GEMM  out = Xh[8192,4096] * Wh[4096,4096]^T + bias
//     CTA 256x128, 8 warps (4x2) of 64x64, mma.sync m16n8k16
// ---------------------------------------------------------------------------
__global__ void __launch_bounds__(256, 1) gemm_kernel(
    float* __restrict__ out, const float* __restrict__ bias,
    const __half* __restrict__ Xh, const __half* __restrict__ Wh) {
    extern __shared__ char smem[];
    const uint32_t sb = smem_u32(smem);
    const int tid = threadIdx.x;
    const int wid = tid >> 5;
    const int lane = tid & 31;

    const int tile_n = blockIdx.x & 31;       // N/128 = 32
    const int tile_m = blockIdx.x >> 5;       // M/256 = 32
    const int warp_m = wid >> 1;              // 0..3
    const int warp_n = wid & 1;               // 0..1

    const char* srcA = (const char*)(Xh + (size_t)tile_m * TILE_M * K_TOTAL);
    const char* srcB = (const char*)(Wh + (size_t)tile_n * TILE_N * K_TOTAL);

    // ---- stage loader (cp.async) ----
    auto load_stage = [&](int slot, int kt) {
        const uint32_t base = sb + slot * STAGE_BYTES;
        const int kb = kt * (KS * 2);                     // byte offset in K
        #pragma unroll
        for (int i = 0; i < 8; i++) {                     // A: 2048 chunks
            int idx = tid + i * 256;
            int row = idx >> 3;
            int cb = (idx & 7) << 4;
            cp_async16(base + swz(row, cb),
                       srcA + (size_t)row * (K_TOTAL * 2) + kb + cb);
        }
        #pragma unroll
        for (int i = 0; i < 4; i++) {                     // B: 1024 chunks
            int idx = tid + i * 256;
            int row = idx >> 3;
            int cb = (idx & 7) << 4;
            cp_async16(base + A_STAGE_BYTES + swz(row, cb),
                       srcB + (size_t)row * (K_TOTAL * 2) + kb + cb);
        }
        cp_commit();
    };

    float c[4][8][4];
    #pragma unroll
    for (int mt = 0; mt < 4; mt++)
        #pragma unroll
        for (int nt = 0; nt < 8; nt++)
            #pragma unroll
            for (int j = 0; j < 4; j++) c[mt][nt][j] = 0.0f;

    // prologue: prefetch 3 stages
    #pragma unroll
    for (int s = 0; s < STAGES - 1; s++) load_stage(s, s);

    // precomputed ldmatrix lane addressing
    const int a_lrow = warp_m * 64 + (lane & 15);         // + mt*16
    const int a_lcb = (lane >> 4) << 4;                   // + ks*32
    const int g = lane >> 3;
    const int b_lrow = warp_n * 64 + ((g >> 1) << 3) + (lane & 7);  // + p*16
    const int b_lcb = (g & 1) << 4;                       // + ks*32

    for (int k = 0; k < K_ITERS; k++) {
        cp_wait2();
        __syncthreads();
        if (k + STAGES - 1 < K_ITERS)
            load_stage((k + STAGES - 1) & (STAGES - 1), k + STAGES - 1);

        const uint32_t sA = sb + (k & (STAGES - 1)) * STAGE_BYTES;
        const uint32_t sB = sA + A_STAGE_BYTES;

        #pragma unroll
        for (int ks = 0; ks < KS / 16; ks++) {
            const int cb0 = ks * 32;
            uint32_t a[4][4], b[4][4];
            #pragma unroll
            for (int mt = 0; mt < 4; mt++) {
                int row = a_lrow + mt * 16;
                ldsm_x4(a[mt][0], a[mt][1], a[mt][2], a[mt][3],
                        sA + swz(row, cb0 + a_lcb));
            }
            #pragma unroll
            for (int p = 0; p < 4; p++) {
                int row = b_lrow + p * 16;
                ldsm_x4(b[p][0], b[p][1], b[p][2], b[p][3],
                        sB + swz(row, cb0 + b_lcb));
            }
            #pragma unroll
            for (int mt = 0; mt < 4; mt++)
                #pragma unroll
                for (int nt = 0; nt < 8; nt++) {
                    const int p = nt >> 1;
                    if (nt & 1)
                        mma16816(c[mt][nt], a[mt], b[p][2], b[p][3]);
                    else
                        mma16816(c[mt][nt], a[mt], b[p][0], b[p][1]);
                }
        }
        __syncthreads();
    }

    // ---- epilogue: fused bias, float2 stores ----
    const int n_base = tile_n * TILE_N + warp_n * 64 + (lane & 3) * 2;
    float2 bv[8];
    #pragma unroll
    for (int nt = 0; nt < 8; nt++)
        bv[nt] = *(const float2*)(bias + n_base + nt * 8);

    const int m_base = tile_m * TILE_M + warp_m * 64 + (lane >> 2);
    #pragma unroll
    for (int mt = 0; mt < 4; mt++) {
        const size_t r0 = (size_t)(m_base + mt * 16) * N_TOTAL;
        const size_t r1 = r0 + 8 * N_TOTAL;
        #pragma unroll
        for (int nt = 0; nt < 8; nt++) {
            const int nc = n_base + nt * 8;
            float2 v0 = make_float2(c[mt][nt][0] + bv[nt].x,
                                    c[mt][nt][1] + bv[nt].y);
            float2 v1 = make_float2(c[mt][nt][2] + bv[nt].x,
                                    c[mt][nt][3] + bv[nt].y);
            *(float2*)(out + r0 + nc) = v0;
            *(float2*)(out + r1 + nc) = v1;
        }
    }
}

// ---------------------------------------------------------------------------
extern "C" void kernel_launch(void* const* d_in, const int* in_sizes, int n_in,
                              void* d_out, int out_size) {
    (void)in_sizes; (void)n_in; (void)out_size;
    const float* x = (const float*)d_in[0];
    const float* W = (const float*)d_in[1];
    const float* b = (const float*)d_in[2];
    float* out = (float*)d_out;

    void *wh_p = nullptr, *xh_p = nullptr;
    cudaGetSymbolAddress(&wh_p, g_Wh);
    cudaGetSymbolAddress(&xh_p, g_Xh);

    fwht_w_kernel<<<N_TOTAL, 256>>>(W, (__half*)wh_p);
    convert_x_kernel<<<2048, 256>>>((const float4*)x, (__half2*)xh_p,
                                    (M_TOTAL * K_TOTAL) / 4);

    static bool cfg = false;
    if (!cfg) {
        cudaFuncSetAttribute(gemm_kernel,
                             cudaFuncAttributeMaxDynamicSharedMemorySize,
                             SMEM_TOTAL);
        cfg = true;
    }
    gemm_kernel<<<(M_TOTAL / TILE_M) * (N_TOTAL / TILE_N), 256, SMEM_TOTAL>>>(
        out, b, (const __half*)xh_p, (const __half*)wh_p);
}

// round 3
// speedup vs baseline: 1.1048x; 1.1048x over previous
#include <cuda_runtime.h>
#include <cuda_fp16.h>
#include <cstdint>

// ============================================================================
// out[8192,4096] = fwht(x) @ W^T + b  ==  x @ fwht(W)^T + b   (H symmetric)
//  K1: Wh = fp16(fwht(W rows) / 64)   -- 3-pass register FWHT, swizzled smem
//  K2: Xh = fp16(x)
//  K3: fp16 HMMA GEMM (mma.sync m16n8k16, fp32 accum), 256x128 tile,
//      4-stage cp.async pipeline, double-buffered frags, fused bias.
// ============================================================================

#define M_TOTAL 8192
#define N_TOTAL 4096
#define K_TOTAL 4096

#define TILE_M 256
#define TILE_N 128
#define KS 64
#define STAGES 4
#define K_ITERS (K_TOTAL / KS)

#define A_STAGE_BYTES (TILE_M * 128)
#define B_STAGE_BYTES (TILE_N * 128)
#define STAGE_BYTES   (A_STAGE_BYTES + B_STAGE_BYTES)
#define SMEM_TOTAL    (STAGES * STAGE_BYTES)            // 196608

__device__ __align__(1024) __half g_Wh[(size_t)N_TOTAL * K_TOTAL];
__device__ __align__(1024) __half g_Xh[(size_t)M_TOTAL * K_TOTAL];

// ---------------------------------------------------------------------------
__device__ __forceinline__ uint32_t smem_u32(const void* p) {
    uint32_t a;
    asm("{ .reg .u64 t; cvta.to.shared.u64 t, %1; cvt.u32.u64 %0, t; }"
        : "=r"(a) : "l"(p));
    return a;
}
__device__ __forceinline__ void cp_async16(uint32_t dst, const void* src) {
    asm volatile("cp.async.cg.shared.global [%0], [%1], 16;" :: "r"(dst), "l"(src));
}
__device__ __forceinline__ void cp_commit() {
    asm volatile("cp.async.commit_group;" ::: "memory");
}
__device__ __forceinline__ void cp_wait2() {
    asm volatile("cp.async.wait_group 2;" ::: "memory");
}
__device__ __forceinline__ void ldsm_x4(uint32_t* r, uint32_t a) {
    asm volatile("ldmatrix.sync.aligned.m8n8.x4.shared.b16 {%0,%1,%2,%3}, [%4];"
                 : "=r"(r[0]), "=r"(r[1]), "=r"(r[2]), "=r"(r[3]) : "r"(a));
}
__device__ __forceinline__ void mma16816(float* c, const uint32_t* a,
                                         uint32_t b0, uint32_t b1) {
    asm volatile(
        "mma.sync.aligned.m16n8k16.row.col.f32.f16.f16.f32 "
        "{%0,%1,%2,%3}, {%4,%5,%6,%7}, {%8,%9}, {%0,%1,%2,%3};"
        : "+f"(c[0]), "+f"(c[1]), "+f"(c[2]), "+f"(c[3])
        : "r"(a[0]), "r"(a[1]), "r"(a[2]), "r"(a[3]), "r"(b0), "r"(b1));
}
__device__ __forceinline__ uint32_t swz(int row, int cb) {
    return (uint32_t)(row * 128 + (cb ^ ((row & 7) << 4)));
}

// ---------------------------------------------------------------------------
// K1: per-row FWHT of W (3 register passes, 2 smem round trips)
//     butterfly stages over distinct index bits commute.
// ---------------------------------------------------------------------------
__device__ __forceinline__ void bfly16(float* r) {
    #pragma unroll
    for (int h = 1; h < 16; h <<= 1)
        #pragma unroll
        for (int i = 0; i < 16; i++)
            if (!(i & h)) {
                float a = r[i], b = r[i + h];
                r[i] = a + b;
                r[i + h] = a - b;
            }
}
// bank swizzle: conflict-free for all 3 pass patterns
__device__ __forceinline__ int fw_phys(int idx) {
    return idx ^ ((idx >> 5) & 15) ^ (((idx >> 8) & 1) << 4);
}

__global__ void __launch_bounds__(256) fwht_w_kernel(const float* __restrict__ W,
                                                     __half* __restrict__ Wh) {
    __shared__ float s[4096];
    const int t = threadIdx.x;
    const float* src = W + (size_t)blockIdx.x * 4096;
    float r[16];

    // pass A: bits 0-3 (idx = t*16 + j), from global
    #pragma unroll
    for (int j = 0; j < 16; j += 4) {
        float4 v = *(const float4*)(src + t * 16 + j);
        r[j] = v.x; r[j + 1] = v.y; r[j + 2] = v.z; r[j + 3] = v.w;
    }
    bfly16(r);
    #pragma unroll
    for (int j = 0; j < 16; j++) s[fw_phys(t * 16 + j)] = r[j];
    __syncthreads();

    // pass B: bits 4-7 (idx = hi<<8 | j<<4 | lo)
    const int hi = t >> 4, lo = t & 15;
    #pragma unroll
    for (int j = 0; j < 16; j++) r[j] = s[fw_phys((hi << 8) | (j << 4) | lo)];
    bfly16(r);
    #pragma unroll
    for (int j = 0; j < 16; j++) s[fw_phys((hi << 8) | (j << 4) | lo)] = r[j];
    __syncthreads();

    // pass C: bits 8-11 (idx = j<<8 | t), store to global
    #pragma unroll
    for (int j = 0; j < 16; j++) r[j] = s[fw_phys((j << 8) | t)];
    bfly16(r);
    __half* dst = Wh + (size_t)blockIdx.x * 4096;
    #pragma unroll
    for (int j = 0; j < 16; j++)
        dst[(j << 8) | t] = __float2half(r[j] * 0.015625f);
}

// ---------------------------------------------------------------------------
// K2: x fp32 -> fp16
// ---------------------------------------------------------------------------
__global__ void __launch_bounds__(256) convert_x_kernel(const float4* __restrict__ x,
                                                        __half2* __restrict__ xh,
                                                        int n4) {
    int i = blockIdx.x * blockDim.x + threadIdx.x;
    int stride = gridDim.x * blockDim.x;
    for (; i < n4; i += stride) {
        float4 v = x[i];
        xh[2 * i]     = __floats2half2_rn(v.x, v.y);
        xh[2 * i + 1] = __floats2half2_rn(v.z, v.w);
    }
}

// ---------------------------------------------------------------------------
// K3: GEMM  out = Xh[8192,4096] * Wh[4096,4096]^T + bias
// ---------------------------------------------------------------------------
__global__ void __launch_bounds__(256, 1) gemm_kernel(
    float* __restrict__ out, const float* __restrict__ bias,
    const __half* __restrict__ Xh, const __half* __restrict__ Wh) {
    extern __shared__ char smem[];
    const uint32_t sb = smem_u32(smem);
    const int tid = threadIdx.x;
    const int wid = tid >> 5;
    const int lane = tid & 31;

    const int tile_n = blockIdx.x & 31;
    const int tile_m = blockIdx.x >> 5;
    const int warp_m = wid >> 1;
    const int warp_n = wid & 1;

    const char* srcA = (const char*)(Xh + (size_t)tile_m * TILE_M * K_TOTAL);
    const char* srcB = (const char*)(Wh + (size_t)tile_n * TILE_N * K_TOTAL);

    auto load_stage = [&](int slot, int kt) {
        const uint32_t base = sb + slot * STAGE_BYTES;
        const int kb = kt * (KS * 2);
        #pragma unroll
        for (int i = 0; i < 8; i++) {
            int idx = tid + i * 256;
            int row = idx >> 3;
            int cb = (idx & 7) << 4;
            cp_async16(base + swz(row, cb),
                       srcA + (size_t)row * (K_TOTAL * 2) + kb + cb);
        }
        #pragma unroll
        for (int i = 0; i < 4; i++) {
            int idx = tid + i * 256;
            int row = idx >> 3;
            int cb = (idx & 7) << 4;
            cp_async16(base + A_STAGE_BYTES + swz(row, cb),
                       srcB + (size_t)row * (K_TOTAL * 2) + kb + cb);
        }
        cp_commit();
    };

    float c[4][8][4];
    #pragma unroll
    for (int mt = 0; mt < 4; mt++)
        #pragma unroll
        for (int nt = 0; nt < 8; nt++)
            #pragma unroll
            for (int j = 0; j < 4; j++) c[mt][nt][j] = 0.0f;

    #pragma unroll
    for (int s = 0; s < STAGES - 1; s++) load_stage(s, s);

    // stage-relative ldmatrix offsets (ks advances by XOR ks<<5)
    const int a_lrow = warp_m * 64 + (lane & 15);
    const int a_lcb = (lane >> 4) << 4;
    const int g = lane >> 3;
    const int b_lrow = warp_n * 64 + ((g >> 1) << 3) + (lane & 7);
    const int b_lcb = (g & 1) << 4;
    uint32_t offA[4], offB[4];
    #pragma unroll
    for (int mt = 0; mt < 4; mt++) offA[mt] = swz(a_lrow + mt * 16, a_lcb);
    #pragma unroll
    for (int p = 0; p < 4; p++) offB[p] = swz(b_lrow + p * 16, b_lcb);

    uint32_t a[2][4][4], b[2][4][4];

    for (int k = 0; k < K_ITERS; k++) {
        cp_wait2();
        __syncthreads();

        const uint32_t sA = sb + (k & (STAGES - 1)) * STAGE_BYTES;
        const uint32_t sB = sA + A_STAGE_BYTES;

        // prime frag buffer 0 (ks = 0)
        #pragma unroll
        for (int mt = 0; mt < 4; mt++) ldsm_x4(a[0][mt], sA + offA[mt]);
        #pragma unroll
        for (int p = 0; p < 4; p++) ldsm_x4(b[0][p], sB + offB[p]);

        if (k + STAGES - 1 < K_ITERS)
            load_stage((k + STAGES - 1) & (STAGES - 1), k + STAGES - 1);

        #pragma unroll
        for (int ks = 0; ks < KS / 16; ks++) {
            const int cur = ks & 1;
            if (ks < KS / 16 - 1) {
                const int nxt = cur ^ 1;
                const uint32_t kx = (uint32_t)((ks + 1) << 5);
                #pragma unroll
                for (int mt = 0; mt < 4; mt++)
                    ldsm_x4(a[nxt][mt], sA + (offA[mt] ^ kx));
                #pragma unroll
                for (int p = 0; p < 4; p++)
                    ldsm_x4(b[nxt][p], sB + (offB[p] ^ kx));
            }
            #pragma unroll
            for (int mt = 0; mt < 4; mt++)
                #pragma unroll
                for (int nt = 0; nt < 8; nt++) {
                    const int p = nt >> 1;
                    if (nt & 1)
                        mma16816(c[mt][nt], a[cur][mt], b[cur][p][2], b[cur][p][3]);
                    else
                        mma16816(c[mt][nt], a[cur][mt], b[cur][p][0], b[cur][p][1]);
                }
        }
    }

    // ---- epilogue: fused bias, float2 stores ----
    const int n_base = tile_n * TILE_N + warp_n * 64 + (lane & 3) * 2;
    float2 bv[8];
    #pragma unroll
    for (int nt = 0; nt < 8; nt++)
        bv[nt] = *(const float2*)(bias + n_base + nt * 8);

    const int m_base = tile_m * TILE_M + warp_m * 64 + (lane >> 2);
    #pragma unroll
    for (int mt = 0; mt < 4; mt++) {
        const size_t r0 = (size_t)(m_base + mt * 16) * N_TOTAL;
        const size_t r1 = r0 + 8 * N_TOTAL;
        #pragma unroll
        for (int nt = 0; nt < 8; nt++) {
            const int nc = n_base + nt * 8;
            *(float2*)(out + r0 + nc) =
                make_float2(c[mt][nt][0] + bv[nt].x, c[mt][nt][1] + bv[nt].y);
            *(float2*)(out + r1 + nc) =
                make_float2(c[mt][nt][2] + bv[nt].x, c[mt][nt][3] + bv[nt].y);
        }
    }
}

// ---------------------------------------------------------------------------
extern "C" void kernel_launch(void* const* d_in, const int* in_sizes, int n_in,
                              void* d_out, int out_size) {
    (void)in_sizes; (void)n_in; (void)out_size;
    const float* x = (const float*)d_in[0];
    const float* W = (const float*)d_in[1];
    const float* b = (const float*)d_in[2];
    float* out = (float*)d_out;

    void *wh_p = nullptr, *xh_p = nullptr;
    cudaGetSymbolAddress(&wh_p, g_Wh);
    cudaGetSymbolAddress(&xh_p, g_Xh);

    fwht_w_kernel<<<N_TOTAL, 256>>>(W, (__half*)wh_p);
    convert_x_kernel<<<2048, 256>>>((const float4*)x, (__half2*)xh_p,
                                    (M_TOTAL * K_TOTAL) / 4);

    static bool cfg = false;
    if (!cfg) {
        cudaFuncSetAttribute(gemm_kernel,
                             cudaFuncAttributeMaxDynamicSharedMemorySize,
                             SMEM_TOTAL);
        cfg = true;
    }
    gemm_kernel<<<(M_TOTAL / TILE_M) * (N_TOTAL / TILE_N), 256, SMEM_TOTAL>>>(
        out, b, (const __half*)xh_p, (const __half*)wh_p);
}